// round 16
// baseline (speedup 1.0000x reference)
#include <cuda_runtime.h>
#include <cuda_bf16.h>
#include <cstddef>

#define NB    4
#define TT_   64
#define LL    64
#define QCH   256
#define KVCH  64
#define GRP   4
#define PPG   16
#define PTOT  (NB*LL*LL)          // 16384 pixels
#define SCALE 0.25f               // 1/sqrt(PPG)

typedef unsigned long long ull;

// Scratch (device globals; no allocation allowed)
__device__ float g_qk[PTOT * 256];   // qk[p][g*64+e], scale folded in
__device__ float g_w [PTOT * 256];   // w [p][g*64+e]

// ---------- packed fp32x2 helpers ----------
__device__ __forceinline__ ull pack2(float lo, float hi) {
    ull r; asm("mov.b64 %0, {%1,%2};" : "=l"(r) : "f"(lo), "f"(hi)); return r;
}
__device__ __forceinline__ void ffma2(ull& d, ull a, ull b) {
    asm("fma.rn.f32x2 %0, %1, %2, %0;" : "+l"(d) : "l"(a), "l"(b));
}
__device__ __forceinline__ void fadd2(ull& d, ull a) {
    asm("add.rn.f32x2 %0, %0, %1;" : "+l"(d) : "l"(a));
}
__device__ __forceinline__ float2 unpack2(ull v) {
    float lo, hi; asm("mov.b64 {%0,%1}, %2;" : "=f"(lo), "=f"(hi) : "l"(v));
    float2 f; f.x = lo; f.y = hi; return f;
}
__device__ __forceinline__ void cp_async16(unsigned dst, const void* src) {
    asm volatile("cp.async.cg.shared.global [%0], [%1], 16;" :: "r"(dst), "l"(src));
}

// Free reinterpret on 16B-aligned addresses.
union F4U { float4 f; ull u[2]; };

// =====================================================================
// Kernel 1: qk[p][g*64+e] = SCALE * sum_c (q[p]@Wq)[g*16+c] * Wk[e][g*16+c]
// 256 blocks x 256 threads, 64 rows/block, smem 49.6KB, 3 CTAs/SM.
// (Measured-best family; unchanged.)
// =====================================================================
__global__ void __launch_bounds__(256, 3) qk_kernel(const float* __restrict__ q,
                                                    const float* __restrict__ Wq,
                                                    const float* __restrict__ Wk) {
    extern __shared__ float sm[];
    float* sWq = sm;                  // [64][64] chunk of Wq rows (later: sQh)
    float* sQ  = sm + 4096;           // [64][64] chunk of q cols
    float* sWk = sm + 8192;           // [64][66] padded (stride 66)
    float* sQh = sm;                  // aliases sWq after chunk loop
    const int tid = threadIdx.x;
    const int rowBase = blockIdx.x * 64;

    for (int i = tid; i < 2048; i += 256) {
        const int e = i >> 5, cp = i & 31;
        *(float2*)&sWk[e * 66 + cp * 2] = ((const float2*)Wk)[i];
    }

    const int tr = (tid >> 4) * 4;
    const int tc = (tid & 15) * 4;

    ull acc[4][2];
#pragma unroll
    for (int i = 0; i < 4; i++) { acc[i][0] = 0ULL; acc[i][1] = 0ULL; }

    for (int c = 0; c < 4; c++) {
        __syncthreads();   // previous chunk consumed (also orders sWk init)
        {
            const float4* src = (const float4*)(Wq + c * 4096);
            for (int i = tid; i < 1024; i += 256) ((float4*)sWq)[i] = src[i];
        }
        for (int i = tid; i < 1024; i += 256) {
            const int row = i >> 4, c4 = i & 15;
            ((float4*)sQ)[row * 16 + c4] =
                *(const float4*)(q + (size_t)(rowBase + row) * 256 + c * 64 + c4 * 4);
        }
        __syncthreads();

        for (int r = 0; r < 64; r += 4) {
            ull w01[4], w23[4];
#pragma unroll
            for (int kk = 0; kk < 4; kk++) {
                float4 wp = *(const float4*)&sWq[(r + kk) * 64 + tc];
                w01[kk] = pack2(wp.x, wp.y);
                w23[kk] = pack2(wp.z, wp.w);
            }
#pragma unroll
            for (int ri = 0; ri < 4; ri++) {
                float4 qv = *(const float4*)&sQ[(tr + ri) * 64 + r];
                ull q0 = pack2(qv.x, qv.x), q1 = pack2(qv.y, qv.y);
                ull q2 = pack2(qv.z, qv.z), q3 = pack2(qv.w, qv.w);
                ffma2(acc[ri][0], q0, w01[0]); ffma2(acc[ri][1], q0, w23[0]);
                ffma2(acc[ri][0], q1, w01[1]); ffma2(acc[ri][1], q1, w23[1]);
                ffma2(acc[ri][0], q2, w01[2]); ffma2(acc[ri][1], q2, w23[2]);
                ffma2(acc[ri][0], q3, w01[3]); ffma2(acc[ri][1], q3, w23[3]);
            }
        }
    }

    __syncthreads();   // all reads of sWq done before aliasing as sQh
#pragma unroll
    for (int ri = 0; ri < 4; ri++) {
        float2 a = unpack2(acc[ri][0]);
        float2 b = unpack2(acc[ri][1]);
        float4 o; o.x = a.x; o.y = a.y; o.z = b.x; o.w = b.y;
        *(float4*)&sQh[(tr + ri) * 64 + tc] = o;
    }
    __syncthreads();

    // Phase 2: qk[row][g*64+e]; 2 groups per pass (32 wk regs)
    {
        const int e  = tid & 63;
        const int rq = tid >> 6;
#pragma unroll
        for (int gp = 0; gp < 2; gp++) {
            ull wk[2][8];
#pragma unroll
            for (int gg = 0; gg < 2; gg++)
#pragma unroll
                for (int c2 = 0; c2 < 8; c2++)
                    wk[gg][c2] = *(const ull*)&sWk[e * 66 + (gp * 2 + gg) * 16 + c2 * 2];
            for (int rr = 0; rr < 16; rr++) {
                const int row = rq * 16 + rr;
                const float* qh = &sQh[row * 64];
                float* dst = &g_qk[(size_t)(rowBase + row) * 256 + e];
#pragma unroll
                for (int gg = 0; gg < 2; gg++) {
                    const int g = gp * 2 + gg;
                    ull a = 0ULL;
#pragma unroll
                    for (int c2 = 0; c2 < 8; c2++)
                        ffma2(a, *(const ull*)&qh[g * 16 + c2 * 2], wk[gg][c2]);
                    float2 v = unpack2(a);
                    dst[g * 64] = SCALE * (v.x + v.y);
                }
            }
        }
    }
}

// =====================================================================
// Kernel 2: attention, software-pipelined over 8 pixels/block.
// NEW: kv tile stored XOR-SWIZZLED (quad index c4 ^ (t&7), natural row
// width 64) -> cp.async stays 16B-aligned AND all k-reads become
// LDS.128 at the 4-phase floor (was 8-phase conflicted LDS.64 pairs).
// Rest identical to the validated pipelined version. smem 42KB.
// =====================================================================
__global__ void __launch_bounds__(128) attn_kernel(const float* __restrict__ kv) {
    __shared__ __align__(16) float kvs[2][64 * 64];  // swizzled, no pad
    __shared__ __align__(16) float qks[2][256];
    __shared__ __align__(16) ull   sp2[2][2][64];    // [hh][gpair][t]
    __shared__ __align__(16) ull   ps2[4 * 64];      // (e,e) splatted
    __shared__ __align__(16) float wsp[4][256];
    __shared__ float red[4][2];

    const int tid = threadIdx.x;
    const int f4 = tid & 15;
    const int sl = tid >> 4;
    const int t  = tid & 63;
    const int gh = tid >> 6;
    const int pBase = blockIdx.x * 8;

    const unsigned kvs_s = (unsigned)__cvta_generic_to_shared(&kvs[0][0]);
    // swizzled quad for this thread's (tt, f4) slots: tt&7 == sl for tt = sl+8k
    const int sq = (f4 ^ sl) * 4;

    // Prologue: prefetch kv(pixel 0) + load qk(pixel 0)
    {
        const int p = pBase;
        const float* b = kv + (size_t)(p >> 12) * (64ull * 4096ull * 64ull)
                            + (size_t)(p & 4095) * 64;
#pragma unroll
        for (int k = 0; k < 8; k++) {
            const int tt = sl + k * 8;
            cp_async16(kvs_s + (unsigned)(tt * 64 + sq) * 4,
                       b + (size_t)tt * 262144 + f4 * 4);
        }
        asm volatile("cp.async.commit_group;");
        if (tid < 64)
            ((float4*)qks[0])[tid] = ((const float4*)(g_qk + (size_t)p * 256))[tid];
    }

    float4 qreg;   // qk(i+1) prefetch (meaningful for tid < 64)

#pragma unroll
    for (int i = 0; i < 8; i++) {
        const int p   = pBase + i;
        const int cur = i & 1;

        // (a) launch next pixel's loads
        if (i < 7) {
            const int pn = p + 1;
            const float* b = kv + (size_t)(pn >> 12) * (64ull * 4096ull * 64ull)
                                + (size_t)(pn & 4095) * 64;
            const unsigned dstb = kvs_s + (unsigned)(1 - cur) * (64 * 64 * 4);
#pragma unroll
            for (int k = 0; k < 8; k++) {
                const int tt = sl + k * 8;
                cp_async16(dstb + (unsigned)(tt * 64 + sq) * 4,
                           b + (size_t)tt * 262144 + f4 * 4);
            }
            asm volatile("cp.async.commit_group;");
            if (tid < 64)
                qreg = ((const float4*)(g_qk + (size_t)pn * 256))[tid];
            asm volatile("cp.async.wait_group 1;");   // buf[cur] complete
        } else {
            asm volatile("cp.async.wait_group 0;");
        }
        __syncthreads();   // buf[cur] + qks[cur] visible to all

        // (d1) Scores, channel-half split: thread (t, hh=gh), all 4 groups
        // over 32 channels. k via swizzled LDS.128 (4-phase floor).
        {
            const float* krow = &kvs[cur][t * 64];
            const int tx = t & 7;
            const float* qbase = qks[cur];
            ull a0 = 0ULL, a1 = 0ULL, a2 = 0ULL, a3 = 0ULL;
#pragma unroll
            for (int ii = 0; ii < 4; ii++) {
                const int qA = gh * 8 + 2 * ii;      // quads for this 8-float chunk
                F4U ka, kb;
                ka.f = *(const float4*)&krow[(qA ^ tx) * 4];
                kb.f = *(const float4*)&krow[((qA + 1) ^ tx) * 4];
                ull k01 = ka.u[0], k23 = ka.u[1];
                ull k45 = kb.u[0], k67 = kb.u[1];
                const int qoff = gh * 32 + ii * 8;
                F4U q0a, q0b, q1a, q1b, q2a, q2b, q3a, q3b;
                q0a.f = *(const float4*)&qbase[0 * 64 + qoff];
                q0b.f = *(const float4*)&qbase[0 * 64 + qoff + 4];
                q1a.f = *(const float4*)&qbase[1 * 64 + qoff];
                q1b.f = *(const float4*)&qbase[1 * 64 + qoff + 4];
                q2a.f = *(const float4*)&qbase[2 * 64 + qoff];
                q2b.f = *(const float4*)&qbase[2 * 64 + qoff + 4];
                q3a.f = *(const float4*)&qbase[3 * 64 + qoff];
                q3b.f = *(const float4*)&qbase[3 * 64 + qoff + 4];
                ffma2(a0, k01, q0a.u[0]); ffma2(a0, k23, q0a.u[1]);
                ffma2(a0, k45, q0b.u[0]); ffma2(a0, k67, q0b.u[1]);
                ffma2(a1, k01, q1a.u[0]); ffma2(a1, k23, q1a.u[1]);
                ffma2(a1, k45, q1b.u[0]); ffma2(a1, k67, q1b.u[1]);
                ffma2(a2, k01, q2a.u[0]); ffma2(a2, k23, q2a.u[1]);
                ffma2(a2, k45, q2b.u[0]); ffma2(a2, k67, q2b.u[1]);
                ffma2(a3, k01, q3a.u[0]); ffma2(a3, k23, q3a.u[1]);
                ffma2(a3, k45, q3b.u[0]); ffma2(a3, k67, q3b.u[1]);
            }
            float2 v0 = unpack2(a0), v1 = unpack2(a1);
            float2 v2 = unpack2(a2), v3 = unpack2(a3);
            sp2[gh][0][t] = pack2(v0.x + v0.y, v1.x + v1.y);
            sp2[gh][1][t] = pack2(v2.x + v2.y, v3.x + v3.y);
        }
        __syncthreads();

        // (d2) Combine halves + unnormalized exp (thread (t, gpair gh))
        {
            ull P = sp2[0][gh][t];
            fadd2(P, sp2[1][gh][t]);
            float2 s = unpack2(P);
            float e0 = __expf(s.x);
            float e1 = __expf(s.y);

            float q0 = e0, q1 = e1;
#pragma unroll
            for (int o = 16; o > 0; o >>= 1) {
                q0 += __shfl_xor_sync(0xffffffffu, q0, o);
                q1 += __shfl_xor_sync(0xffffffffu, q1, o);
            }
            const int w = tid >> 5;
            if ((tid & 31) == 0) { red[w][0] = q0; red[w][1] = q1; }
            ps2[(2 * gh) * 64 + t]     = pack2(e0, e0);
            ps2[(2 * gh + 1) * 64 + t] = pack2(e1, e1);
        }
        __syncthreads();

        // (d3) AV (unnormalized): swizzled LDS.128 k + splatted ps
        {
            ull acc[4][2];
#pragma unroll
            for (int g = 0; g < 4; g++) { acc[g][0] = 0ULL; acc[g][1] = 0ULL; }
#pragma unroll
            for (int k = 0; k < 8; k++) {
                const int tt = sl + k * 8;
                F4U kq; kq.f = *(const float4*)&kvs[cur][tt * 64 + sq];
                ull k01 = kq.u[0], k23 = kq.u[1];
#pragma unroll
                for (int g = 0; g < 4; g++) {
                    ull pp = ps2[g * 64 + tt];
                    ffma2(acc[g][0], pp, k01);
                    ffma2(acc[g][1], pp, k23);
                }
            }
#pragma unroll
            for (int g = 0; g < 4; g++) {
#pragma unroll
                for (int h = 0; h < 2; h++) {
                    ull o = __shfl_xor_sync(0xffffffffu, acc[g][h], 16);
                    fadd2(acc[g][h], o);
                }
            }
            if ((tid & 16) == 0) {
                const int w = tid >> 5;
#pragma unroll
                for (int g = 0; g < 4; g++) {
                    float2 a = unpack2(acc[g][0]);
                    float2 b = unpack2(acc[g][1]);
                    float4 o; o.x = a.x; o.y = a.y; o.z = b.x; o.w = b.y;
                    *(float4*)&wsp[w][g * 64 + f4 * 4] = o;
                }
            }
        }
        __syncthreads();

        // (d4) Reduce 4 slices, normalize, store w
        {
            const int o = tid * 2;
            const int g = tid >> 5;
            const float inv = 1.0f /
                (red[2 * (g >> 1)][g & 1] + red[2 * (g >> 1) + 1][g & 1]);
            float sx = 0.f, sy = 0.f;
#pragma unroll
            for (int slc = 0; slc < 4; slc++) {
                float2 v = *(const float2*)&wsp[slc][o];
                sx += v.x; sy += v.y;
            }
            float2 r; r.x = sx * inv; r.y = sy * inv;
            *(float2*)&g_w[(size_t)p * 256 + o] = r;
        }

        // (e) hand qk(i+1) to smem; visible after next boundary sync
        if (i < 7 && tid < 64)
            ((float4*)qks[1 - cur])[tid] = qreg;
    }
}

// =====================================================================
// Kernel 3: x[p] = per-group w@Wv ; out[p] = x@Wout + b
// 256 blocks x 256 threads, 64 rows per block. 96KB smem. (Unchanged.)
// =====================================================================
__global__ void __launch_bounds__(256) out_kernel(const float* __restrict__ Wv,
                                                  const float* __restrict__ Wout,
                                                  const float* __restrict__ bias,
                                                  float* __restrict__ out) {
    extern __shared__ float sm[];
    float* sBig = sm;                 // [64][256]: w tile, then Wout
    float* sWv  = sm + 16384;         // [64][64]
    float* sX   = sm + 16384 + 4096;  // [64][64]
    const int tid = threadIdx.x;
    const int rowBase = blockIdx.x * 64;

    for (int i = tid; i < 1024; i += 256) ((float4*)sWv)[i] = ((const float4*)Wv)[i];
    {
        const float4* src = (const float4*)(g_w + (size_t)rowBase * 256);
        for (int i = tid; i < 4096; i += 256) ((float4*)sBig)[i] = src[i];
    }
    __syncthreads();

    // Phase 1: x[row][k] = sum_e w[row][g*64+e] * Wv[e][k], g = k>>4
    {
        const int tr = (tid >> 4) * 4;
        const int tc = (tid & 15) * 4;
        const int g  = tc >> 4;
        ull acc[4][2];
#pragma unroll
        for (int i = 0; i < 4; i++) { acc[i][0] = 0ULL; acc[i][1] = 0ULL; }
        for (int e = 0; e < 64; e++) {
            F4U wv; wv.f = *(const float4*)&sWv[e * 64 + tc];
#pragma unroll
            for (int ri = 0; ri < 4; ri++) {
                float x = sBig[(tr + ri) * 256 + g * 64 + e];
                ull xx = pack2(x, x);
                ffma2(acc[ri][0], xx, wv.u[0]);
                ffma2(acc[ri][1], xx, wv.u[1]);
            }
        }
#pragma unroll
        for (int ri = 0; ri < 4; ri++) {
            float2 a = unpack2(acc[ri][0]);
            float2 b = unpack2(acc[ri][1]);
            float4 o; o.x = a.x; o.y = a.y; o.z = b.x; o.w = b.y;
            *(float4*)&sX[(tr + ri) * 64 + tc] = o;
        }
    }
    __syncthreads();

    // Reload sBig with Wout
    for (int i = tid; i < 4096; i += 256) ((float4*)sBig)[i] = ((const float4*)Wout)[i];
    __syncthreads();

    // Phase 2: out[row][d] = b[d] + sum_k x[row][k]*Wout[k][d]
    {
        const int rg = tid >> 6;
        const int c4 = tid & 63;
        ull acc[16][2];
#pragma unroll
        for (int i = 0; i < 16; i++) { acc[i][0] = 0ULL; acc[i][1] = 0ULL; }
        for (int k = 0; k < 64; k++) {
            F4U wd; wd.f = *(const float4*)&sBig[k * 256 + c4 * 4];
            const float* xcol = &sX[rg * 16 * 64 + k];
#pragma unroll
            for (int rr = 0; rr < 16; rr++) {
                float xv = xcol[rr * 64];
                ull xx = pack2(xv, xv);
                ffma2(acc[rr][0], xx, wd.u[0]);
                ffma2(acc[rr][1], xx, wd.u[1]);
            }
        }
        float4 bv = ((const float4*)bias)[c4];
#pragma unroll
        for (int rr = 0; rr < 16; rr++) {
            float2 a = unpack2(acc[rr][0]);
            float2 b = unpack2(acc[rr][1]);
            float4 o;
            o.x = a.x + bv.x; o.y = a.y + bv.y;
            o.z = b.x + bv.z; o.w = b.y + bv.w;
            *(float4*)&out[(size_t)(rowBase + rg * 16 + rr) * 256 + c4 * 4] = o;
        }
    }
}

extern "C" void kernel_launch(void* const* d_in, const int* in_sizes, int n_in,
                              void* d_out, int out_size) {
    const float* q    = (const float*)d_in[0];
    const float* kv   = (const float*)d_in[1];
    const float* Wq   = (const float*)d_in[2];
    const float* Wk   = (const float*)d_in[3];
    const float* Wv   = (const float*)d_in[4];
    const float* Wout = (const float*)d_in[5];
    const float* bias = (const float*)d_in[6];
    float* out = (float*)d_out;

    cudaFuncSetAttribute(qk_kernel,  cudaFuncAttributeMaxDynamicSharedMemorySize, 49664);
    cudaFuncSetAttribute(out_kernel, cudaFuncAttributeMaxDynamicSharedMemorySize, 98304);

    qk_kernel<<<PTOT / 64, 256, 49664>>>(q, Wq, Wk);
    attn_kernel<<<PTOT / 8, 128>>>(kv);
    out_kernel<<<PTOT / 64, 256, 98304>>>(Wv, Wout, bias, out);
}

// round 17
// speedup vs baseline: 1.5090x; 1.5090x over previous
#include <cuda_runtime.h>
#include <cuda_bf16.h>
#include <cstddef>

#define NB    4
#define TT_   64
#define LL    64
#define QCH   256
#define KVCH  64
#define GRP   4
#define PPG   16
#define PTOT  (NB*LL*LL)          // 16384 pixels
#define SCALE 0.25f               // 1/sqrt(PPG)

typedef unsigned long long ull;

// Scratch (device globals; no allocation allowed)
__device__ float g_qk[PTOT * 256];   // qk[p][g*64+e], scale folded in
__device__ float g_w [PTOT * 256];   // w [p][g*64+e]

// ---------- packed fp32x2 helpers ----------
__device__ __forceinline__ ull pack2(float lo, float hi) {
    ull r; asm("mov.b64 %0, {%1,%2};" : "=l"(r) : "f"(lo), "f"(hi)); return r;
}
__device__ __forceinline__ void ffma2(ull& d, ull a, ull b) {
    asm("fma.rn.f32x2 %0, %1, %2, %0;" : "+l"(d) : "l"(a), "l"(b));
}
__device__ __forceinline__ void fadd2(ull& d, ull a) {
    asm("add.rn.f32x2 %0, %0, %1;" : "+l"(d) : "l"(a));
}
__device__ __forceinline__ float2 unpack2(ull v) {
    float lo, hi; asm("mov.b64 {%0,%1}, %2;" : "=f"(lo), "=f"(hi) : "l"(v));
    float2 f; f.x = lo; f.y = hi; return f;
}
__device__ __forceinline__ void cp_async16(unsigned dst, const void* src) {
    asm volatile("cp.async.cg.shared.global [%0], [%1], 16;" :: "r"(dst), "l"(src));
}

// Free reinterpret on 16B-aligned addresses.
union F4U { float4 f; ull u[2]; };

// =====================================================================
// Kernel 1: qk[p][g*64+e] = SCALE * sum_c (q[p]@Wq)[g*16+c] * Wk[e][g*16+c]
// 256 blocks x 256 threads, 64 rows/block, smem 49.6KB, 3 CTAs/SM.
// (Measured-best family; unchanged — serves as internal clock control.)
// =====================================================================
__global__ void __launch_bounds__(256, 3) qk_kernel(const float* __restrict__ q,
                                                    const float* __restrict__ Wq,
                                                    const float* __restrict__ Wk) {
    extern __shared__ float sm[];
    float* sWq = sm;                  // [64][64] chunk of Wq rows (later: sQh)
    float* sQ  = sm + 4096;           // [64][64] chunk of q cols
    float* sWk = sm + 8192;           // [64][66] padded (stride 66)
    float* sQh = sm;                  // aliases sWq after chunk loop
    const int tid = threadIdx.x;
    const int rowBase = blockIdx.x * 64;

    for (int i = tid; i < 2048; i += 256) {
        const int e = i >> 5, cp = i & 31;
        *(float2*)&sWk[e * 66 + cp * 2] = ((const float2*)Wk)[i];
    }

    const int tr = (tid >> 4) * 4;
    const int tc = (tid & 15) * 4;

    ull acc[4][2];
#pragma unroll
    for (int i = 0; i < 4; i++) { acc[i][0] = 0ULL; acc[i][1] = 0ULL; }

    for (int c = 0; c < 4; c++) {
        __syncthreads();   // previous chunk consumed (also orders sWk init)
        {
            const float4* src = (const float4*)(Wq + c * 4096);
            for (int i = tid; i < 1024; i += 256) ((float4*)sWq)[i] = src[i];
        }
        for (int i = tid; i < 1024; i += 256) {
            const int row = i >> 4, c4 = i & 15;
            ((float4*)sQ)[row * 16 + c4] =
                *(const float4*)(q + (size_t)(rowBase + row) * 256 + c * 64 + c4 * 4);
        }
        __syncthreads();

        for (int r = 0; r < 64; r += 4) {
            ull w01[4], w23[4];
#pragma unroll
            for (int kk = 0; kk < 4; kk++) {
                float4 wp = *(const float4*)&sWq[(r + kk) * 64 + tc];
                w01[kk] = pack2(wp.x, wp.y);
                w23[kk] = pack2(wp.z, wp.w);
            }
#pragma unroll
            for (int ri = 0; ri < 4; ri++) {
                float4 qv = *(const float4*)&sQ[(tr + ri) * 64 + r];
                ull q0 = pack2(qv.x, qv.x), q1 = pack2(qv.y, qv.y);
                ull q2 = pack2(qv.z, qv.z), q3 = pack2(qv.w, qv.w);
                ffma2(acc[ri][0], q0, w01[0]); ffma2(acc[ri][1], q0, w23[0]);
                ffma2(acc[ri][0], q1, w01[1]); ffma2(acc[ri][1], q1, w23[1]);
                ffma2(acc[ri][0], q2, w01[2]); ffma2(acc[ri][1], q2, w23[2]);
                ffma2(acc[ri][0], q3, w01[3]); ffma2(acc[ri][1], q3, w23[3]);
            }
        }
    }

    __syncthreads();   // all reads of sWq done before aliasing as sQh
#pragma unroll
    for (int ri = 0; ri < 4; ri++) {
        float2 a = unpack2(acc[ri][0]);
        float2 b = unpack2(acc[ri][1]);
        float4 o; o.x = a.x; o.y = a.y; o.z = b.x; o.w = b.y;
        *(float4*)&sQh[(tr + ri) * 64 + tc] = o;
    }
    __syncthreads();

    // Phase 2: qk[row][g*64+e]; 2 groups per pass (32 wk regs)
    {
        const int e  = tid & 63;
        const int rq = tid >> 6;
#pragma unroll
        for (int gp = 0; gp < 2; gp++) {
            ull wk[2][8];
#pragma unroll
            for (int gg = 0; gg < 2; gg++)
#pragma unroll
                for (int c2 = 0; c2 < 8; c2++)
                    wk[gg][c2] = *(const ull*)&sWk[e * 66 + (gp * 2 + gg) * 16 + c2 * 2];
            for (int rr = 0; rr < 16; rr++) {
                const int row = rq * 16 + rr;
                const float* qh = &sQh[row * 64];
                float* dst = &g_qk[(size_t)(rowBase + row) * 256 + e];
#pragma unroll
                for (int gg = 0; gg < 2; gg++) {
                    const int g = gp * 2 + gg;
                    ull a = 0ULL;
#pragma unroll
                    for (int c2 = 0; c2 < 8; c2++)
                        ffma2(a, *(const ull*)&qh[g * 16 + c2 * 2], wk[gg][c2]);
                    float2 v = unpack2(a);
                    dst[g * 64] = SCALE * (v.x + v.y);
                }
            }
        }
    }
}

// =====================================================================
// Kernel 2: attention, software-pipelined over 8 pixels/block.
// kv tile XOR-SWIZZLED (quad index c4 ^ (t&7), natural row width 64):
// cp.async stays 16B-aligned AND all k-reads are LDS.128 at the
// 4-phase floor. Identical to R16 (re-bench: R16 run was ~1.44x
// degraded per the qk internal control).
// =====================================================================
__global__ void __launch_bounds__(128) attn_kernel(const float* __restrict__ kv) {
    __shared__ __align__(16) float kvs[2][64 * 64];  // swizzled, no pad
    __shared__ __align__(16) float qks[2][256];
    __shared__ __align__(16) ull   sp2[2][2][64];    // [hh][gpair][t]
    __shared__ __align__(16) ull   ps2[4 * 64];      // (e,e) splatted
    __shared__ __align__(16) float wsp[4][256];
    __shared__ float red[4][2];

    const int tid = threadIdx.x;
    const int f4 = tid & 15;
    const int sl = tid >> 4;
    const int t  = tid & 63;
    const int gh = tid >> 6;
    const int pBase = blockIdx.x * 8;

    const unsigned kvs_s = (unsigned)__cvta_generic_to_shared(&kvs[0][0]);
    // swizzled quad for this thread's (tt, f4) slots: tt&7 == sl for tt = sl+8k
    const int sq = (f4 ^ sl) * 4;

    // Prologue: prefetch kv(pixel 0) + load qk(pixel 0)
    {
        const int p = pBase;
        const float* b = kv + (size_t)(p >> 12) * (64ull * 4096ull * 64ull)
                            + (size_t)(p & 4095) * 64;
#pragma unroll
        for (int k = 0; k < 8; k++) {
            const int tt = sl + k * 8;
            cp_async16(kvs_s + (unsigned)(tt * 64 + sq) * 4,
                       b + (size_t)tt * 262144 + f4 * 4);
        }
        asm volatile("cp.async.commit_group;");
        if (tid < 64)
            ((float4*)qks[0])[tid] = ((const float4*)(g_qk + (size_t)p * 256))[tid];
    }

    float4 qreg;   // qk(i+1) prefetch (meaningful for tid < 64)

#pragma unroll
    for (int i = 0; i < 8; i++) {
        const int p   = pBase + i;
        const int cur = i & 1;

        // (a) launch next pixel's loads
        if (i < 7) {
            const int pn = p + 1;
            const float* b = kv + (size_t)(pn >> 12) * (64ull * 4096ull * 64ull)
                                + (size_t)(pn & 4095) * 64;
            const unsigned dstb = kvs_s + (unsigned)(1 - cur) * (64 * 64 * 4);
#pragma unroll
            for (int k = 0; k < 8; k++) {
                const int tt = sl + k * 8;
                cp_async16(dstb + (unsigned)(tt * 64 + sq) * 4,
                           b + (size_t)tt * 262144 + f4 * 4);
            }
            asm volatile("cp.async.commit_group;");
            if (tid < 64)
                qreg = ((const float4*)(g_qk + (size_t)pn * 256))[tid];
            asm volatile("cp.async.wait_group 1;");   // buf[cur] complete
        } else {
            asm volatile("cp.async.wait_group 0;");
        }
        __syncthreads();   // buf[cur] + qks[cur] visible to all

        // (d1) Scores, channel-half split: thread (t, hh=gh), all 4 groups
        // over 32 channels. k via swizzled LDS.128 (4-phase floor).
        {
            const float* krow = &kvs[cur][t * 64];
            const int tx = t & 7;
            const float* qbase = qks[cur];
            ull a0 = 0ULL, a1 = 0ULL, a2 = 0ULL, a3 = 0ULL;
#pragma unroll
            for (int ii = 0; ii < 4; ii++) {
                const int qA = gh * 8 + 2 * ii;      // quads for this 8-float chunk
                F4U ka, kb;
                ka.f = *(const float4*)&krow[(qA ^ tx) * 4];
                kb.f = *(const float4*)&krow[((qA + 1) ^ tx) * 4];
                ull k01 = ka.u[0], k23 = ka.u[1];
                ull k45 = kb.u[0], k67 = kb.u[1];
                const int qoff = gh * 32 + ii * 8;
                F4U q0a, q0b, q1a, q1b, q2a, q2b, q3a, q3b;
                q0a.f = *(const float4*)&qbase[0 * 64 + qoff];
                q0b.f = *(const float4*)&qbase[0 * 64 + qoff + 4];
                q1a.f = *(const float4*)&qbase[1 * 64 + qoff];
                q1b.f = *(const float4*)&qbase[1 * 64 + qoff + 4];
                q2a.f = *(const float4*)&qbase[2 * 64 + qoff];
                q2b.f = *(const float4*)&qbase[2 * 64 + qoff + 4];
                q3a.f = *(const float4*)&qbase[3 * 64 + qoff];
                q3b.f = *(const float4*)&qbase[3 * 64 + qoff + 4];
                ffma2(a0, k01, q0a.u[0]); ffma2(a0, k23, q0a.u[1]);
                ffma2(a0, k45, q0b.u[0]); ffma2(a0, k67, q0b.u[1]);
                ffma2(a1, k01, q1a.u[0]); ffma2(a1, k23, q1a.u[1]);
                ffma2(a1, k45, q1b.u[0]); ffma2(a1, k67, q1b.u[1]);
                ffma2(a2, k01, q2a.u[0]); ffma2(a2, k23, q2a.u[1]);
                ffma2(a2, k45, q2b.u[0]); ffma2(a2, k67, q2b.u[1]);
                ffma2(a3, k01, q3a.u[0]); ffma2(a3, k23, q3a.u[1]);
                ffma2(a3, k45, q3b.u[0]); ffma2(a3, k67, q3b.u[1]);
            }
            float2 v0 = unpack2(a0), v1 = unpack2(a1);
            float2 v2 = unpack2(a2), v3 = unpack2(a3);
            sp2[gh][0][t] = pack2(v0.x + v0.y, v1.x + v1.y);
            sp2[gh][1][t] = pack2(v2.x + v2.y, v3.x + v3.y);
        }
        __syncthreads();

        // (d2) Combine halves + unnormalized exp (thread (t, gpair gh))
        {
            ull P = sp2[0][gh][t];
            fadd2(P, sp2[1][gh][t]);
            float2 s = unpack2(P);
            float e0 = __expf(s.x);
            float e1 = __expf(s.y);

            float q0 = e0, q1 = e1;
#pragma unroll
            for (int o = 16; o > 0; o >>= 1) {
                q0 += __shfl_xor_sync(0xffffffffu, q0, o);
                q1 += __shfl_xor_sync(0xffffffffu, q1, o);
            }
            const int w = tid >> 5;
            if ((tid & 31) == 0) { red[w][0] = q0; red[w][1] = q1; }
            ps2[(2 * gh) * 64 + t]     = pack2(e0, e0);
            ps2[(2 * gh + 1) * 64 + t] = pack2(e1, e1);
        }
        __syncthreads();

        // (d3) AV (unnormalized): swizzled LDS.128 k + splatted ps
        {
            ull acc[4][2];
#pragma unroll
            for (int g = 0; g < 4; g++) { acc[g][0] = 0ULL; acc[g][1] = 0ULL; }
#pragma unroll
            for (int k = 0; k < 8; k++) {
                const int tt = sl + k * 8;
                F4U kq; kq.f = *(const float4*)&kvs[cur][tt * 64 + sq];
                ull k01 = kq.u[0], k23 = kq.u[1];
#pragma unroll
                for (int g = 0; g < 4; g++) {
                    ull pp = ps2[g * 64 + tt];
                    ffma2(acc[g][0], pp, k01);
                    ffma2(acc[g][1], pp, k23);
                }
            }
#pragma unroll
            for (int g = 0; g < 4; g++) {
#pragma unroll
                for (int h = 0; h < 2; h++) {
                    ull o = __shfl_xor_sync(0xffffffffu, acc[g][h], 16);
                    fadd2(acc[g][h], o);
                }
            }
            if ((tid & 16) == 0) {
                const int w = tid >> 5;
#pragma unroll
                for (int g = 0; g < 4; g++) {
                    float2 a = unpack2(acc[g][0]);
                    float2 b = unpack2(acc[g][1]);
                    float4 o; o.x = a.x; o.y = a.y; o.z = b.x; o.w = b.y;
                    *(float4*)&wsp[w][g * 64 + f4 * 4] = o;
                }
            }
        }
        __syncthreads();

        // (d4) Reduce 4 slices, normalize, store w
        {
            const int o = tid * 2;
            const int g = tid >> 5;
            const float inv = 1.0f /
                (red[2 * (g >> 1)][g & 1] + red[2 * (g >> 1) + 1][g & 1]);
            float sx = 0.f, sy = 0.f;
#pragma unroll
            for (int slc = 0; slc < 4; slc++) {
                float2 v = *(const float2*)&wsp[slc][o];
                sx += v.x; sy += v.y;
            }
            float2 r; r.x = sx * inv; r.y = sy * inv;
            *(float2*)&g_w[(size_t)p * 256 + o] = r;
        }

        // (e) hand qk(i+1) to smem; visible after next boundary sync
        if (i < 7 && tid < 64)
            ((float4*)qks[1 - cur])[tid] = qreg;
    }
}

// =====================================================================
// Kernel 3: x[p] = per-group w@Wv ; out[p] = x@Wout + b
// 256 blocks x 256 threads, 64 rows per block. 96KB smem. (Unchanged.)
// =====================================================================
__global__ void __launch_bounds__(256) out_kernel(const float* __restrict__ Wv,
                                                  const float* __restrict__ Wout,
                                                  const float* __restrict__ bias,
                                                  float* __restrict__ out) {
    extern __shared__ float sm[];
    float* sBig = sm;                 // [64][256]: w tile, then Wout
    float* sWv  = sm + 16384;         // [64][64]
    float* sX   = sm + 16384 + 4096;  // [64][64]
    const int tid = threadIdx.x;
    const int rowBase = blockIdx.x * 64;

    for (int i = tid; i < 1024; i += 256) ((float4*)sWv)[i] = ((const float4*)Wv)[i];
    {
        const float4* src = (const float4*)(g_w + (size_t)rowBase * 256);
        for (int i = tid; i < 4096; i += 256) ((float4*)sBig)[i] = src[i];
    }
    __syncthreads();

    // Phase 1: x[row][k] = sum_e w[row][g*64+e] * Wv[e][k], g = k>>4
    {
        const int tr = (tid >> 4) * 4;
        const int tc = (tid & 15) * 4;
        const int g  = tc >> 4;
        ull acc[4][2];
#pragma unroll
        for (int i = 0; i < 4; i++) { acc[i][0] = 0ULL; acc[i][1] = 0ULL; }
        for (int e = 0; e < 64; e++) {
            F4U wv; wv.f = *(const float4*)&sWv[e * 64 + tc];
#pragma unroll
            for (int ri = 0; ri < 4; ri++) {
                float x = sBig[(tr + ri) * 256 + g * 64 + e];
                ull xx = pack2(x, x);
                ffma2(acc[ri][0], xx, wv.u[0]);
                ffma2(acc[ri][1], xx, wv.u[1]);
            }
        }
#pragma unroll
        for (int ri = 0; ri < 4; ri++) {
            float2 a = unpack2(acc[ri][0]);
            float2 b = unpack2(acc[ri][1]);
            float4 o; o.x = a.x; o.y = a.y; o.z = b.x; o.w = b.y;
            *(float4*)&sX[(tr + ri) * 64 + tc] = o;
        }
    }
    __syncthreads();

    // Reload sBig with Wout
    for (int i = tid; i < 4096; i += 256) ((float4*)sBig)[i] = ((const float4*)Wout)[i];
    __syncthreads();

    // Phase 2: out[row][d] = b[d] + sum_k x[row][k]*Wout[k][d]
    {
        const int rg = tid >> 6;
        const int c4 = tid & 63;
        ull acc[16][2];
#pragma unroll
        for (int i = 0; i < 16; i++) { acc[i][0] = 0ULL; acc[i][1] = 0ULL; }
        for (int k = 0; k < 64; k++) {
            F4U wd; wd.f = *(const float4*)&sBig[k * 256 + c4 * 4];
            const float* xcol = &sX[rg * 16 * 64 + k];
#pragma unroll
            for (int rr = 0; rr < 16; rr++) {
                float xv = xcol[rr * 64];
                ull xx = pack2(xv, xv);
                ffma2(acc[rr][0], xx, wd.u[0]);
                ffma2(acc[rr][1], xx, wd.u[1]);
            }
        }
        float4 bv = ((const float4*)bias)[c4];
#pragma unroll
        for (int rr = 0; rr < 16; rr++) {
            float2 a = unpack2(acc[rr][0]);
            float2 b = unpack2(acc[rr][1]);
            float4 o;
            o.x = a.x + bv.x; o.y = a.y + bv.y;
            o.z = b.x + bv.z; o.w = b.y + bv.w;
            *(float4*)&out[(size_t)(rowBase + rg * 16 + rr) * 256 + c4 * 4] = o;
        }
    }
}

extern "C" void kernel_launch(void* const* d_in, const int* in_sizes, int n_in,
                              void* d_out, int out_size) {
    const float* q    = (const float*)d_in[0];
    const float* kv   = (const float*)d_in[1];
    const float* Wq   = (const float*)d_in[2];
    const float* Wk   = (const float*)d_in[3];
    const float* Wv   = (const float*)d_in[4];
    const float* Wout = (const float*)d_in[5];
    const float* bias = (const float*)d_in[6];
    float* out = (float*)d_out;

    cudaFuncSetAttribute(qk_kernel,  cudaFuncAttributeMaxDynamicSharedMemorySize, 49664);
    cudaFuncSetAttribute(out_kernel, cudaFuncAttributeMaxDynamicSharedMemorySize, 98304);

    qk_kernel<<<PTOT / 64, 256, 49664>>>(q, Wq, Wk);
    attn_kernel<<<PTOT / 8, 128>>>(kv);
    out_kernel<<<PTOT / 64, 256, 98304>>>(Wv, Wout, bias, out);
}